// round 1
// baseline (speedup 1.0000x reference)
#include <cuda_runtime.h>
#include <cstdint>

// ---------------------------------------------------------------------------
// NetVLAD on GB300 — round 0: fp32 + packed f32x2 FMA baseline
// shapes: N=32, C=1024, H*W=S=784 (padded to SP=800), D=128, K=64, OUT=1024
// ---------------------------------------------------------------------------

#define SP 800   // padded spatial extent (784 -> 800), pad columns are zero

// scratch (device globals; no allocation allowed)
__device__ float g_WpoolT[1024 * 128];        // [c][d]
__device__ float g_xf   [32 * 128 * SP];      // normalized descriptors [n][d][s]
__device__ float g_sa   [32 * 64  * SP];      // softmax assignments   [n][k][s]
__device__ float g_sasum[32 * 64];            // sum_s sa
__device__ float g_vlad [32 * 8192];          // intra-normalized vlad [n][k*128+d]
__device__ float g_proj [32 * 1024];          // projection accumulators

#define FMA2(acc, a, b) \
    asm("fma.rn.f32x2 %0, %1, %2, %0;" : "+l"(acc) : "l"(a), "l"(b))

// ---------------------------------------------------------------------------
// kT: transpose Wpool (D=128, C=1024) -> WpoolT (C, D)
// ---------------------------------------------------------------------------
__global__ void kT(const float* __restrict__ Wpool) {
    int idx = blockIdx.x * 256 + threadIdx.x;
    if (idx < 128 * 1024) {
        int c = idx >> 7, d = idx & 127;
        g_WpoolT[idx] = Wpool[d * 1024 + c];
    }
}

// ---------------------------------------------------------------------------
// kZ: zero the accumulators (must re-run every replay)
// ---------------------------------------------------------------------------
__global__ void kZ() {
    int idx = blockIdx.x * 256 + threadIdx.x;
    if (idx < 32 * 64)   g_sasum[idx] = 0.f;
    if (idx < 32 * 1024) g_proj[idx]  = 0.f;
}

// ---------------------------------------------------------------------------
// kA: pool GEMM (f32x2) + bias + column L2 norm + assignment logits + softmax
// grid (25 s-tiles, 32 n), 256 threads, dynamic smem 54016 B
// smem float offsets:
//   [0, 2112)      Ws[16][132]  (GEMM)   -> reused as WconvS[64][128] (8192)
//   [2112, 3200)   xs2[16][68]  duplicated-pair x tile
//   [8192, 12416)  xfS[128][33]
//   [12416,13472)  part[32][33] (norm partials, softmax partials)
//   [13472,13504)  cinv[32]
// ---------------------------------------------------------------------------
__global__ void __launch_bounds__(256) kA(const float* __restrict__ x,
                                          const float* __restrict__ bpool,
                                          const float* __restrict__ Wconv,
                                          const float* __restrict__ bconv) {
    extern __shared__ float sm[];
    const int OFF_WS = 0;
    const int OFF_XS = 2112;
    const int OFF_XF = 8192;
    const int OFF_PART = 12416;
    const int OFF_CINV = 13472;

    const int tid = threadIdx.x;
    const int n = blockIdx.y;
    const int s0 = blockIdx.x * 32;
    const int td = tid >> 3;   // 0..31 : d-rows td*4..td*4+3
    const int ts = tid & 7;    // 0..7  : s-cols ts*4..ts*4+3

    unsigned long long acc[2][4];
#pragma unroll
    for (int a = 0; a < 2; a++)
#pragma unroll
        for (int b = 0; b < 4; b++) acc[a][b] = 0ull;

    const int ld_cc = tid >> 4;        // 0..15
    const int ld_d  = (tid & 15) * 8;
    const int ld_s  = (tid & 15) * 2;

    const float* xn = x + (size_t)n * 1024 * 784;

    for (int c0 = 0; c0 < 1024; c0 += 16) {
        __syncthreads();
        // W tile: Ws[cc][d] (conflict-free via WpoolT)
        float4 w0 = *(const float4*)&g_WpoolT[(c0 + ld_cc) * 128 + ld_d];
        float4 w1 = *(const float4*)&g_WpoolT[(c0 + ld_cc) * 128 + ld_d + 4];
        *(float4*)&sm[OFF_WS + ld_cc * 132 + ld_d]     = w0;
        *(float4*)&sm[OFF_WS + ld_cc * 132 + ld_d + 4] = w1;
        // X tile with duplicated pairs: (v,v) per column -> direct f32x2 operand
        int sc0 = s0 + ld_s, sc1 = sc0 + 1;
        float v0 = (sc0 < 784) ? xn[(c0 + ld_cc) * 784 + sc0] : 0.f;
        float v1 = (sc1 < 784) ? xn[(c0 + ld_cc) * 784 + sc1] : 0.f;
        float4 dp; dp.x = v0; dp.y = v0; dp.z = v1; dp.w = v1;
        *(float4*)&sm[OFF_XS + ld_cc * 68 + ld_s * 2] = dp;
        __syncthreads();
#pragma unroll
        for (int cc = 0; cc < 16; cc++) {
            const ulonglong2 wv   = *(const ulonglong2*)&sm[OFF_WS + cc * 132 + td * 4];
            const ulonglong2 x01  = *(const ulonglong2*)&sm[OFF_XS + cc * 68 + ts * 8];
            const ulonglong2 x23  = *(const ulonglong2*)&sm[OFF_XS + cc * 68 + ts * 8 + 4];
            FMA2(acc[0][0], wv.x, x01.x); FMA2(acc[1][0], wv.y, x01.x);
            FMA2(acc[0][1], wv.x, x01.y); FMA2(acc[1][1], wv.y, x01.y);
            FMA2(acc[0][2], wv.x, x23.x); FMA2(acc[1][2], wv.y, x23.x);
            FMA2(acc[0][3], wv.x, x23.y); FMA2(acc[1][3], wv.y, x23.y);
        }
    }

    // unpack accumulators -> p[d_sub][s_sub], add bias
    float p[4][4];
#pragma unroll
    for (int j = 0; j < 4; j++) {
        float a0, a1, a2, a3;
        asm("mov.b64 {%0,%1}, %2;" : "=f"(a0), "=f"(a1) : "l"(acc[0][j]));
        asm("mov.b64 {%0,%1}, %2;" : "=f"(a2), "=f"(a3) : "l"(acc[1][j]));
        p[0][j] = a0; p[1][j] = a1; p[2][j] = a2; p[3][j] = a3;
    }
#pragma unroll
    for (int i = 0; i < 4; i++) {
        float b = bpool[td * 4 + i];
#pragma unroll
        for (int j = 0; j < 4; j++) p[i][j] += b;
    }

    // column L2 norms over d
#pragma unroll
    for (int j = 0; j < 4; j++) {
        float s = 0.f;
#pragma unroll
        for (int i = 0; i < 4; i++) s += p[i][j] * p[i][j];
        sm[OFF_PART + (ts * 4 + j) * 33 + td] = s;
    }
    __syncthreads();
    if (tid < 32) {
        float s = 0.f;
#pragma unroll
        for (int t = 0; t < 32; t++) s += sm[OFF_PART + tid * 33 + t];
        sm[OFF_CINV + tid] = 1.f / fmaxf(sqrtf(s), 1e-12f);
    }
    __syncthreads();

    // normalize, write xf (global, zero-padded) and xfS (smem)
    float* xfn = g_xf + (size_t)n * 128 * SP;
    const bool colv = (s0 + ts * 4) < 784;
#pragma unroll
    for (int i = 0; i < 4; i++) {
        float vv[4];
#pragma unroll
        for (int j = 0; j < 4; j++) {
            vv[j] = colv ? p[i][j] * sm[OFF_CINV + ts * 4 + j] : 0.f;
            sm[OFF_XF + (td * 4 + i) * 33 + ts * 4 + j] = vv[j];
        }
        float4 o; o.x = vv[0]; o.y = vv[1]; o.z = vv[2]; o.w = vv[3];
        *(float4*)&xfn[(td * 4 + i) * SP + s0 + ts * 4] = o;
    }

    // load Wconv into smem (overwrites GEMM staging region; safe post-syncs)
#pragma unroll
    for (int r = 0; r < 8; r++)
        *(float4*)&sm[OFF_WS + r * 1024 + tid * 4] =
            *(const float4*)&Wconv[r * 1024 + tid * 4];
    __syncthreads();

    // assignment logits: thread = (warp tk -> 8 k's, lane -> 1 column)
    const int tk = tid >> 5;
    const int lane = tid & 31;
    float l[8];
#pragma unroll
    for (int i = 0; i < 8; i++) l[i] = bconv[tk * 8 + i];
    for (int d = 0; d < 128; d++) {
        float xv = sm[OFF_XF + d * 33 + lane];
#pragma unroll
        for (int i = 0; i < 8; i++)
            l[i] += sm[OFF_WS + (tk * 8 + i) * 128 + d] * xv;
    }

    // softmax over K=64 (8 values x 8 warps per column)
    float m = l[0];
#pragma unroll
    for (int i = 1; i < 8; i++) m = fmaxf(m, l[i]);
    sm[OFF_PART + tk * 33 + lane] = m;
    __syncthreads();
    float M = sm[OFF_PART + lane];
#pragma unroll
    for (int t = 1; t < 8; t++) M = fmaxf(M, sm[OFF_PART + t * 33 + lane]);
    float e[8], ssum = 0.f;
#pragma unroll
    for (int i = 0; i < 8; i++) { e[i] = __expf(l[i] - M); ssum += e[i]; }
    sm[OFF_PART + (8 + tk) * 33 + lane] = ssum;
    __syncthreads();
    float tot = 0.f;
#pragma unroll
    for (int t = 0; t < 8; t++) tot += sm[OFF_PART + (8 + t) * 33 + lane];
    float rinv = 1.f / tot;

    const int scol = s0 + lane;
    const bool valid = scol < 784;
    float* san = g_sa + (size_t)n * 64 * SP;
#pragma unroll
    for (int i = 0; i < 8; i++) {
        float v = valid ? e[i] * rinv : 0.f;
        san[(tk * 8 + i) * SP + scol] = v;
        float r = v;
#pragma unroll
        for (int off = 16; off; off >>= 1)
            r += __shfl_xor_sync(0xffffffffu, r, off);
        if (lane == 0) atomicAdd(&g_sasum[n * 64 + tk * 8 + i], r);
    }
}

// ---------------------------------------------------------------------------
// kB: vlad = sa @ xf^T - centroids * sasum, fused intra-norm over K
// grid (4 d-tiles, 32 n), 256 threads
// ---------------------------------------------------------------------------
__global__ void __launch_bounds__(256) kB(const float* __restrict__ centroids) {
    __shared__ float saS[64 * 20];
    __shared__ float xfS[32 * 21];
    __shared__ float red[32 * 33];
    __shared__ float dinv[32];

    const int tid = threadIdx.x;
    const int dt = blockIdx.x;   // d-tile: d in [dt*32, dt*32+32)
    const int n = blockIdx.y;
    const int tk = tid >> 3;     // 0..31 -> k = tk*2 + {0,1}
    const int dd = tid & 7;      // d local = dd*4 + e

    float acc0[4] = {0, 0, 0, 0}, acc1[4] = {0, 0, 0, 0};
    const float* san = g_sa + (size_t)n * 64 * SP;
    const float* xfn = g_xf + (size_t)n * 128 * SP + (size_t)dt * 32 * SP;
    const int lk = tid >> 2;           // 0..63
    const int loff = (tid & 3) * 4;    // 0,4,8,12

    for (int s0 = 0; s0 < SP; s0 += 16) {
        __syncthreads();
        float4 sv = *(const float4*)&san[lk * SP + s0 + loff];
        *(float4*)&saS[lk * 20 + loff] = sv;
        if (tid < 128) {
            int dl = tid >> 2;
            float4 xv = *(const float4*)&xfn[dl * SP + s0 + loff];
            xfS[dl * 21 + loff + 0] = xv.x;
            xfS[dl * 21 + loff + 1] = xv.y;
            xfS[dl * 21 + loff + 2] = xv.z;
            xfS[dl * 21 + loff + 3] = xv.w;
        }
        __syncthreads();
#pragma unroll
        for (int ss = 0; ss < 16; ss++) {
            float sv0 = saS[(tk * 2) * 20 + ss];
            float sv1 = saS[(tk * 2 + 1) * 20 + ss];
#pragma unroll
            for (int e2 = 0; e2 < 4; e2++) {
                float xv = xfS[(dd * 4 + e2) * 21 + ss];
                acc0[e2] += sv0 * xv;
                acc1[e2] += sv1 * xv;
            }
        }
    }

    float sA = g_sasum[n * 64 + tk * 2];
    float sB = g_sasum[n * 64 + tk * 2 + 1];
    float v0[4], v1[4];
#pragma unroll
    for (int e2 = 0; e2 < 4; e2++) {
        int dg = dt * 32 + dd * 4 + e2;
        v0[e2] = acc0[e2] - centroids[(tk * 2) * 128 + dg] * sA;
        v1[e2] = acc1[e2] - centroids[(tk * 2 + 1) * 128 + dg] * sB;
        red[(dd * 4 + e2) * 33 + tk] = v0[e2] * v0[e2] + v1[e2] * v1[e2];
    }
    __syncthreads();
    if (tid < 32) {
        float s = 0.f;
#pragma unroll
        for (int t = 0; t < 32; t++) s += red[tid * 33 + t];
        dinv[tid] = 1.f / fmaxf(sqrtf(s), 1e-12f);
    }
    __syncthreads();
    float* vn = g_vlad + (size_t)n * 8192;
#pragma unroll
    for (int e2 = 0; e2 < 4; e2++) {
        int dg = dt * 32 + dd * 4 + e2;
        float iv = dinv[dd * 4 + e2];
        vn[(tk * 2) * 128 + dg]     = v0[e2] * iv;
        vn[(tk * 2 + 1) * 128 + dg] = v1[e2] * iv;
    }
}

// ---------------------------------------------------------------------------
// kC: projection out += vlad @ Wproj^T, j-split for occupancy
// grid (32 o-tiles, 8 j-chunks), 512 threads
// ---------------------------------------------------------------------------
__global__ void __launch_bounds__(512) kC(const float* __restrict__ Wproj) {
    __shared__ float vs[32 * 69];
    const int tid = threadIdx.x;
    const int o = blockIdx.x * 32 + (tid >> 4);
    const int tn = (tid & 15) * 2;
    const int jbase = blockIdx.y * 1024;
    const int ln = tid >> 4;         // 0..31
    const int lj = (tid & 15) * 4;   // 0..60
    float acc0 = 0.f, acc1 = 0.f;

    for (int jt = 0; jt < 1024; jt += 64) {
        __syncthreads();
        float4 v = *(const float4*)&g_vlad[ln * 8192 + jbase + jt + lj];
        vs[ln * 69 + lj + 0] = v.x;
        vs[ln * 69 + lj + 1] = v.y;
        vs[ln * 69 + lj + 2] = v.z;
        vs[ln * 69 + lj + 3] = v.w;
        __syncthreads();
        const float* wrow = Wproj + (size_t)o * 8192 + jbase + jt;
#pragma unroll
        for (int q = 0; q < 16; q++) {
            float4 w = *(const float4*)&wrow[q * 4];
            const float wv[4] = {w.x, w.y, w.z, w.w};
#pragma unroll
            for (int u = 0; u < 4; u++) {
                acc0 += wv[u] * vs[tn * 69 + q * 4 + u];
                acc1 += wv[u] * vs[(tn + 1) * 69 + q * 4 + u];
            }
        }
    }
    atomicAdd(&g_proj[tn * 1024 + o], acc0);
    atomicAdd(&g_proj[(tn + 1) * 1024 + o], acc1);
}

// ---------------------------------------------------------------------------
// kD: bias + final L2 norm -> output
// grid 32, 256 threads
// ---------------------------------------------------------------------------
__global__ void __launch_bounds__(256) kD(const float* __restrict__ bproj,
                                          float* __restrict__ out) {
    __shared__ float wr[8];
    __shared__ float inv_s;
    const int n = blockIdx.x, tid = threadIdx.x;
    float v[4]; float ps = 0.f;
#pragma unroll
    for (int r = 0; r < 4; r++) {
        int o = r * 256 + tid;
        v[r] = g_proj[n * 1024 + o] + bproj[o];
        ps += v[r] * v[r];
    }
#pragma unroll
    for (int off = 16; off; off >>= 1)
        ps += __shfl_xor_sync(0xffffffffu, ps, off);
    if ((tid & 31) == 0) wr[tid >> 5] = ps;
    __syncthreads();
    if (tid == 0) {
        float s = 0.f;
#pragma unroll
        for (int t = 0; t < 8; t++) s += wr[t];
        inv_s = 1.f / fmaxf(sqrtf(s), 1e-12f);
    }
    __syncthreads();
#pragma unroll
    for (int r = 0; r < 4; r++)
        out[n * 1024 + r * 256 + tid] = v[r] * inv_s;
}

// ---------------------------------------------------------------------------
extern "C" void kernel_launch(void* const* d_in, const int* in_sizes, int n_in,
                              void* d_out, int out_size) {
    const float* x         = (const float*)d_in[0];
    const float* Wpool     = (const float*)d_in[1];
    const float* bpool     = (const float*)d_in[2];
    const float* Wconv     = (const float*)d_in[3];
    const float* bconv     = (const float*)d_in[4];
    const float* centroids = (const float*)d_in[5];
    const float* Wproj     = (const float*)d_in[6];
    const float* bproj     = (const float*)d_in[7];
    float* out = (float*)d_out;

    cudaFuncSetAttribute(kA, cudaFuncAttributeMaxDynamicSharedMemorySize, 56000);

    kT<<<512, 256>>>(Wpool);
    kZ<<<128, 256>>>();
    dim3 gA(25, 32);
    kA<<<gA, 256, 54016>>>(x, bpool, Wconv, bconv);
    dim3 gB(4, 32);
    kB<<<gB, 256>>>(centroids);
    dim3 gC(32, 8);
    kC<<<gC, 512>>>(Wproj);
    kD<<<32, 256>>>(bproj, out);
}

// round 2
// speedup vs baseline: 1.6612x; 1.6612x over previous
#include <cuda_runtime.h>
#include <cstdint>

// ---------------------------------------------------------------------------
// NetVLAD on GB300 — round 1: compute-bound fp32x2 restructure
// N=32, C=1024, S=784 (pad 896), D=128, K=64, OUT=1024
// ---------------------------------------------------------------------------

#define SP 896   // padded spatial extent; pad columns forced to zero

__device__ float g_WpoolT[1024 * 128];        // [c][d]
__device__ float g_xf   [32 * 128 * SP];      // [n][d][s]
__device__ float g_sa   [32 * 64  * SP];      // [n][k][s]
__device__ float g_sasum[32 * 64];
__device__ float g_vlad [32 * 8192];
__device__ float g_proj [32 * 1024];

#define FMA2(acc, a, b) \
    asm("fma.rn.f32x2 %0, %1, %2, %0;" : "+l"(acc) : "l"(a), "l"(b))
#define DUP2(d, s) \
    asm("mov.b64 %0, {%1, %1};" : "=l"(d) : "f"(s))
#define UNPK(lo, hi, s) \
    asm("mov.b64 {%0, %1}, %2;" : "=f"(lo), "=f"(hi) : "l"(s))

// ---------------------------------------------------------------------------
__global__ void kT(const float* __restrict__ Wpool) {
    int idx = blockIdx.x * 256 + threadIdx.x;
    if (idx < 128 * 1024) {
        int c = idx >> 7, d = idx & 127;
        g_WpoolT[idx] = Wpool[d * 1024 + c];
    }
}

__global__ void kZ() {
    int idx = blockIdx.x * 256 + threadIdx.x;
    if (idx < 32 * 64)   g_sasum[idx] = 0.f;
    if (idx < 32 * 1024) g_proj[idx]  = 0.f;
}

// ---------------------------------------------------------------------------
// kA: pool GEMM (128d x 128s per block) + bias + col L2 norm + logits + softmax
// grid (7 s-tiles, 32 n), 256 threads, dyn smem 111616 B
// float offsets:
//   region A [0, 8704): Ws[16][132] (0..2112) + Xs[16][132] (2112..4224)
//                        later reused as WconvT[128][68]  (0..8704)
//   [8704, 25600)  xfS[128][132]
//   [25600, 27776) part[128][17]  (also reused as [64][34])
//   [27776, 27904) colbuf[128]    (cinv / softmax max / softmax 1/sum)
// ---------------------------------------------------------------------------
__global__ void __launch_bounds__(256) kA(const float* __restrict__ x,
                                          const float* __restrict__ bpool,
                                          const float* __restrict__ Wconv,
                                          const float* __restrict__ bconv) {
    extern __shared__ float sm[];
    const int OFF_WS = 0, OFF_XS = 2112, OFF_WCT = 0;
    const int OFF_XF = 8704, OFF_PART = 25600, OFF_COL = 27776;

    const int tid = threadIdx.x;
    const int n = blockIdx.y;
    const int s0 = blockIdx.x * 128;
    const int gs = tid >> 4;     // 0..15 -> s base gs*8
    const int gd = tid & 15;     // 0..15 -> d base gd*8

    unsigned long long acc[4][8];
#pragma unroll
    for (int p = 0; p < 4; p++)
#pragma unroll
        for (int j = 0; j < 8; j++) acc[p][j] = 0ull;

    const int stc = tid >> 4;          // 0..15 : cc row for staging
    const int st8 = (tid & 15) * 8;    // 0..120: col base for staging

    const float* xn = x + (size_t)n * 1024 * 784;
    const bool fullv = (s0 + 128) <= 784;

    for (int c0 = 0; c0 < 1024; c0 += 16) {
        __syncthreads();
        // W tile [cc][d]
        {
            const float* wr = &g_WpoolT[(c0 + stc) * 128 + st8];
            float4 w0 = *(const float4*)&wr[0];
            float4 w1 = *(const float4*)&wr[4];
            *(float4*)&sm[OFF_WS + stc * 132 + st8]     = w0;
            *(float4*)&sm[OFF_WS + stc * 132 + st8 + 4] = w1;
        }
        // X tile [cc][s]
        {
            const float* xr = &xn[(c0 + stc) * 784];
            float4 x0, x1;
            if (fullv) {
                x0 = *(const float4*)&xr[s0 + st8];
                x1 = *(const float4*)&xr[s0 + st8 + 4];
            } else {
                float t[8];
#pragma unroll
                for (int u = 0; u < 8; u++) {
                    int sc = s0 + st8 + u;
                    t[u] = (sc < 784) ? xr[sc] : 0.f;
                }
                x0.x = t[0]; x0.y = t[1]; x0.z = t[2]; x0.w = t[3];
                x1.x = t[4]; x1.y = t[5]; x1.z = t[6]; x1.w = t[7];
            }
            *(float4*)&sm[OFF_XS + stc * 132 + st8]     = x0;
            *(float4*)&sm[OFF_XS + stc * 132 + st8 + 4] = x1;
        }
        __syncthreads();
#pragma unroll
        for (int cc = 0; cc < 16; cc++) {
            ulonglong2 w0 = *(const ulonglong2*)&sm[OFF_WS + cc * 132 + gd * 8];
            ulonglong2 w1 = *(const ulonglong2*)&sm[OFF_WS + cc * 132 + gd * 8 + 4];
            float4 xl = *(const float4*)&sm[OFF_XS + cc * 132 + gs * 8];
            float4 xh = *(const float4*)&sm[OFF_XS + cc * 132 + gs * 8 + 4];
            unsigned long long xd[8];
            DUP2(xd[0], xl.x); DUP2(xd[1], xl.y); DUP2(xd[2], xl.z); DUP2(xd[3], xl.w);
            DUP2(xd[4], xh.x); DUP2(xd[5], xh.y); DUP2(xd[6], xh.z); DUP2(xd[7], xh.w);
#pragma unroll
            for (int j = 0; j < 8; j++) {
                FMA2(acc[0][j], w0.x, xd[j]);
                FMA2(acc[1][j], w0.y, xd[j]);
                FMA2(acc[2][j], w1.x, xd[j]);
                FMA2(acc[3][j], w1.y, xd[j]);
            }
        }
    }

    // ---- unpack + bias ----
    float pv[8][8];
#pragma unroll
    for (int p = 0; p < 4; p++)
#pragma unroll
        for (int j = 0; j < 8; j++)
            UNPK(pv[2 * p][j], pv[2 * p + 1][j], acc[p][j]);
#pragma unroll
    for (int i = 0; i < 8; i++) {
        float b = bpool[gd * 8 + i];
#pragma unroll
        for (int j = 0; j < 8; j++) pv[i][j] += b;
    }

    // ---- column L2 norm over d ----
#pragma unroll
    for (int j = 0; j < 8; j++) {
        float s = 0.f;
#pragma unroll
        for (int i = 0; i < 8; i++) s += pv[i][j] * pv[i][j];
        sm[OFF_PART + (gs * 8 + j) * 17 + gd] = s;
    }
    __syncthreads();
    if (tid < 128) {
        float s = 0.f;
#pragma unroll
        for (int t = 0; t < 16; t++) s += sm[OFF_PART + tid * 17 + t];
        sm[OFF_COL + tid] = 1.f / fmaxf(sqrtf(s), 1e-12f);
    }
    __syncthreads();

    // ---- normalize (zero pad cols), write xf (gmem) + xfS (smem) ----
#pragma unroll
    for (int j = 0; j < 8; j++) {
        bool v = (s0 + gs * 8 + j) < 784;
        float m = v ? sm[OFF_COL + gs * 8 + j] : 0.f;
#pragma unroll
        for (int i = 0; i < 8; i++) pv[i][j] *= m;
    }
    float* xfn = g_xf + (size_t)n * 128 * SP;
#pragma unroll
    for (int i = 0; i < 8; i++) {
        int d = gd * 8 + i;
        float4 o0, o1;
        o0.x = pv[i][0]; o0.y = pv[i][1]; o0.z = pv[i][2]; o0.w = pv[i][3];
        o1.x = pv[i][4]; o1.y = pv[i][5]; o1.z = pv[i][6]; o1.w = pv[i][7];
        *(float4*)&xfn[(size_t)d * SP + s0 + gs * 8]     = o0;
        *(float4*)&xfn[(size_t)d * SP + s0 + gs * 8 + 4] = o1;
        *(float4*)&sm[OFF_XF + d * 132 + gs * 8]     = o0;
        *(float4*)&sm[OFF_XF + d * 132 + gs * 8 + 4] = o1;
    }

    // ---- stage WconvT [d][k] (overwrites Ws/Xs region) ----
    {
        int kr = tid & 63, dg = tid >> 6;   // cols dg*32..+31
#pragma unroll
        for (int u = 0; u < 8; u++) {
            float4 w = *(const float4*)&Wconv[kr * 128 + dg * 32 + u * 4];
            sm[OFF_WCT + (dg * 32 + u * 4 + 0) * 68 + kr] = w.x;
            sm[OFF_WCT + (dg * 32 + u * 4 + 1) * 68 + kr] = w.y;
            sm[OFF_WCT + (dg * 32 + u * 4 + 2) * 68 + kr] = w.z;
            sm[OFF_WCT + (dg * 32 + u * 4 + 3) * 68 + kr] = w.w;
        }
    }
    __syncthreads();

    // ---- logits: a2[kpair][4 s], FMA2 over k-pairs ----
    const int kg = tid & 7;      // k base kg*8
    const int sc = tid >> 3;     // 0..31, s base sc*4
    unsigned long long a2[4][4];
#pragma unroll
    for (int p = 0; p < 4; p++)
#pragma unroll
        for (int j = 0; j < 4; j++) a2[p][j] = 0ull;
    for (int d = 0; d < 128; d++) {
        ulonglong2 w0 = *(const ulonglong2*)&sm[OFF_WCT + d * 68 + kg * 8];
        ulonglong2 w1 = *(const ulonglong2*)&sm[OFF_WCT + d * 68 + kg * 8 + 4];
        float4 xv = *(const float4*)&sm[OFF_XF + d * 132 + sc * 4];
        unsigned long long xd[4];
        DUP2(xd[0], xv.x); DUP2(xd[1], xv.y); DUP2(xd[2], xv.z); DUP2(xd[3], xv.w);
#pragma unroll
        for (int j = 0; j < 4; j++) {
            FMA2(a2[0][j], w0.x, xd[j]);
            FMA2(a2[1][j], w0.y, xd[j]);
            FMA2(a2[2][j], w1.x, xd[j]);
            FMA2(a2[3][j], w1.y, xd[j]);
        }
    }
    float l[8][4];
#pragma unroll
    for (int p = 0; p < 4; p++)
#pragma unroll
        for (int j = 0; j < 4; j++)
            UNPK(l[2 * p][j], l[2 * p + 1][j], a2[p][j]);
#pragma unroll
    for (int i = 0; i < 8; i++) {
        float b = bconv[kg * 8 + i];
#pragma unroll
        for (int j = 0; j < 4; j++) l[i][j] += b;
    }

    // ---- softmax over K=64 per column ----
#pragma unroll
    for (int j = 0; j < 4; j++) {
        float m = l[0][j];
#pragma unroll
        for (int i = 1; i < 8; i++) m = fmaxf(m, l[i][j]);
        sm[OFF_PART + (sc * 4 + j) * 17 + kg] = m;
    }
    __syncthreads();
    if (tid < 128) {
        float m = sm[OFF_PART + tid * 17];
#pragma unroll
        for (int t = 1; t < 8; t++) m = fmaxf(m, sm[OFF_PART + tid * 17 + t]);
        sm[OFF_COL + tid] = m;
    }
    __syncthreads();
    float e[8][4];
#pragma unroll
    for (int j = 0; j < 4; j++) {
        float M = sm[OFF_COL + sc * 4 + j];
        float ssum = 0.f;
#pragma unroll
        for (int i = 0; i < 8; i++) { e[i][j] = __expf(l[i][j] - M); ssum += e[i][j]; }
        sm[OFF_PART + (sc * 4 + j) * 17 + kg] = ssum;
    }
    __syncthreads();
    if (tid < 128) {
        float t = 0.f;
#pragma unroll
        for (int q = 0; q < 8; q++) t += sm[OFF_PART + tid * 17 + q];
        sm[OFF_COL + tid] = 1.f / t;
    }
    __syncthreads();

    // ---- write sa (zero pad cols) + sasum partials ----
    float ps[8];
#pragma unroll
    for (int i = 0; i < 8; i++) ps[i] = 0.f;
    float* san = g_sa + (size_t)n * 64 * SP;
#pragma unroll
    for (int j = 0; j < 4; j++) {
        int sl = sc * 4 + j;
        bool v = (s0 + sl) < 784;
        float r = v ? sm[OFF_COL + sl] : 0.f;
#pragma unroll
        for (int i = 0; i < 8; i++) {
            float val = e[i][j] * r;
            san[(size_t)(kg * 8 + i) * SP + s0 + sl] = val;
            ps[i] += val;
        }
    }
    __syncthreads();   // part buffer reuse as [64][34]
#pragma unroll
    for (int i = 0; i < 8; i++)
        sm[OFF_PART + (kg * 8 + i) * 34 + sc] = ps[i];
    __syncthreads();
    if (tid < 64) {
        float s = 0.f;
#pragma unroll
        for (int c = 0; c < 32; c++) s += sm[OFF_PART + tid * 34 + c];
        atomicAdd(&g_sasum[n * 64 + tid], s);
    }
}

// ---------------------------------------------------------------------------
// kB: vlad = sa @ xf^T - centroids * sasum, fused intra-norm over K
// grid (4 d-tiles of 32, 32 n), 256 threads
// ---------------------------------------------------------------------------
__global__ void __launch_bounds__(256) kB(const float* __restrict__ centroids) {
    __shared__ float saT[32 * 68];   // [ss][k]
    __shared__ float xfT[32 * 36];   // [ss][dloc]
    __shared__ float red[32 * 17];
    __shared__ float dinv[32];

    const int tid = threadIdx.x;
    const int dt = blockIdx.x;
    const int n = blockIdx.y;
    const int tk = tid >> 4;     // k base tk*4
    const int td = tid & 15;     // d pair base td*2

    unsigned long long acc[4];
#pragma unroll
    for (int q = 0; q < 4; q++) acc[q] = 0ull;

    const int skr = tid & 63, scg = tid >> 6;   // sa stage
    const int xdr = tid & 31, xcg = tid >> 5;   // xf stage
    const float* san = g_sa + (size_t)n * 64 * SP;
    const float* xfn = g_xf + (size_t)n * 128 * SP + (size_t)dt * 32 * SP;

    for (int sb = 0; sb < SP; sb += 32) {
        __syncthreads();
        {
            float4 a = *(const float4*)&san[(size_t)skr * SP + sb + scg * 8];
            float4 b = *(const float4*)&san[(size_t)skr * SP + sb + scg * 8 + 4];
            saT[(scg * 8 + 0) * 68 + skr] = a.x;
            saT[(scg * 8 + 1) * 68 + skr] = a.y;
            saT[(scg * 8 + 2) * 68 + skr] = a.z;
            saT[(scg * 8 + 3) * 68 + skr] = a.w;
            saT[(scg * 8 + 4) * 68 + skr] = b.x;
            saT[(scg * 8 + 5) * 68 + skr] = b.y;
            saT[(scg * 8 + 6) * 68 + skr] = b.z;
            saT[(scg * 8 + 7) * 68 + skr] = b.w;
            float4 c = *(const float4*)&xfn[(size_t)xdr * SP + sb + xcg * 4];
            xfT[(xcg * 4 + 0) * 36 + xdr] = c.x;
            xfT[(xcg * 4 + 1) * 36 + xdr] = c.y;
            xfT[(xcg * 4 + 2) * 36 + xdr] = c.z;
            xfT[(xcg * 4 + 3) * 36 + xdr] = c.w;
        }
        __syncthreads();
#pragma unroll
        for (int ss = 0; ss < 32; ss++) {
            float4 sv = *(const float4*)&saT[ss * 68 + tk * 4];
            unsigned long long xp = *(const unsigned long long*)&xfT[ss * 36 + td * 2];
            unsigned long long d0, d1, d2, d3;
            DUP2(d0, sv.x); DUP2(d1, sv.y); DUP2(d2, sv.z); DUP2(d3, sv.w);
            FMA2(acc[0], d0, xp);
            FMA2(acc[1], d1, xp);
            FMA2(acc[2], d2, xp);
            FMA2(acc[3], d3, xp);
        }
    }

    float v[4][2];
#pragma unroll
    for (int q = 0; q < 4; q++) {
        UNPK(v[q][0], v[q][1], acc[q]);
        float sq = g_sasum[n * 64 + tk * 4 + q];
#pragma unroll
        for (int r = 0; r < 2; r++) {
            int dg = dt * 32 + td * 2 + r;
            v[q][r] -= centroids[(tk * 4 + q) * 128 + dg] * sq;
        }
    }
#pragma unroll
    for (int r = 0; r < 2; r++) {
        float s = 0.f;
#pragma unroll
        for (int q = 0; q < 4; q++) s += v[q][r] * v[q][r];
        red[(td * 2 + r) * 17 + tk] = s;
    }
    __syncthreads();
    if (tid < 32) {
        float s = 0.f;
#pragma unroll
        for (int t = 0; t < 16; t++) s += red[tid * 17 + t];
        dinv[tid] = 1.f / fmaxf(sqrtf(s), 1e-12f);
    }
    __syncthreads();
    float* vn = g_vlad + (size_t)n * 8192;
#pragma unroll
    for (int q = 0; q < 4; q++)
#pragma unroll
        for (int r = 0; r < 2; r++) {
            int dg = dt * 32 + td * 2 + r;
            vn[(tk * 4 + q) * 128 + dg] = v[q][r] * dinv[td * 2 + r];
        }
}

// ---------------------------------------------------------------------------
// kC: proj += vlad @ Wproj^T.  grid (32 o-tiles of 32, 4 j-splits), 128 thr
// ---------------------------------------------------------------------------
__global__ void __launch_bounds__(128) kC(const float* __restrict__ Wproj) {
    __shared__ float wS[32 * 68];   // [o][j]
    __shared__ float vT[64 * 36];   // [j][n]

    const int tid = threadIdx.x;
    const int ob = blockIdx.x * 32;
    const int jb = blockIdx.y * 2048;
    const int to = tid >> 2;      // o local 0..31
    const int ng = tid & 3;       // n base ng*8

    unsigned long long acc[4];
#pragma unroll
    for (int q = 0; q < 4; q++) acc[q] = 0ull;

    const int sr = tid & 31, scg = tid >> 5;   // staging: row, col-group*16

    for (int jt = 0; jt < 2048; jt += 64) {
        __syncthreads();
        {
            const float* wr = &Wproj[(size_t)(ob + sr) * 8192 + jb + jt + scg * 16];
#pragma unroll
            for (int u = 0; u < 4; u++)
                *(float4*)&wS[sr * 68 + scg * 16 + u * 4] = *(const float4*)&wr[u * 4];
            const float* vr = &g_vlad[(size_t)sr * 8192 + jb + jt + scg * 16];
#pragma unroll
            for (int u = 0; u < 4; u++) {
                float4 v4 = *(const float4*)&vr[u * 4];
                vT[(scg * 16 + u * 4 + 0) * 36 + sr] = v4.x;
                vT[(scg * 16 + u * 4 + 1) * 36 + sr] = v4.y;
                vT[(scg * 16 + u * 4 + 2) * 36 + sr] = v4.z;
                vT[(scg * 16 + u * 4 + 3) * 36 + sr] = v4.w;
            }
        }
        __syncthreads();
#pragma unroll
        for (int j = 0; j < 64; j++) {
            float w = wS[to * 68 + j];
            ulonglong2 v0 = *(const ulonglong2*)&vT[j * 36 + ng * 8];
            ulonglong2 v1 = *(const ulonglong2*)&vT[j * 36 + ng * 8 + 4];
            unsigned long long wd;
            DUP2(wd, w);
            FMA2(acc[0], wd, v0.x);
            FMA2(acc[1], wd, v0.y);
            FMA2(acc[2], wd, v1.x);
            FMA2(acc[3], wd, v1.y);
        }
    }
#pragma unroll
    for (int q = 0; q < 4; q++) {
        float lo, hi;
        UNPK(lo, hi, acc[q]);
        atomicAdd(&g_proj[(ng * 8 + 2 * q) * 1024 + ob + to], lo);
        atomicAdd(&g_proj[(ng * 8 + 2 * q + 1) * 1024 + ob + to], hi);
    }
}

// ---------------------------------------------------------------------------
// kD: bias + final L2 norm -> output
// ---------------------------------------------------------------------------
__global__ void __launch_bounds__(256) kD(const float* __restrict__ bproj,
                                          float* __restrict__ out) {
    __shared__ float wr[8];
    __shared__ float inv_s;
    const int n = blockIdx.x, tid = threadIdx.x;
    float v[4]; float ps = 0.f;
#pragma unroll
    for (int r = 0; r < 4; r++) {
        int o = r * 256 + tid;
        v[r] = g_proj[n * 1024 + o] + bproj[o];
        ps += v[r] * v[r];
    }
#pragma unroll
    for (int off = 16; off; off >>= 1)
        ps += __shfl_xor_sync(0xffffffffu, ps, off);
    if ((tid & 31) == 0) wr[tid >> 5] = ps;
    __syncthreads();
    if (tid == 0) {
        float s = 0.f;
#pragma unroll
        for (int t = 0; t < 8; t++) s += wr[t];
        inv_s = 1.f / fmaxf(sqrtf(s), 1e-12f);
    }
    __syncthreads();
#pragma unroll
    for (int r = 0; r < 4; r++)
        out[n * 1024 + r * 256 + tid] = v[r] * inv_s;
}

// ---------------------------------------------------------------------------
extern "C" void kernel_launch(void* const* d_in, const int* in_sizes, int n_in,
                              void* d_out, int out_size) {
    const float* x         = (const float*)d_in[0];
    const float* Wpool     = (const float*)d_in[1];
    const float* bpool     = (const float*)d_in[2];
    const float* Wconv     = (const float*)d_in[3];
    const float* bconv     = (const float*)d_in[4];
    const float* centroids = (const float*)d_in[5];
    const float* Wproj     = (const float*)d_in[6];
    const float* bproj     = (const float*)d_in[7];
    float* out = (float*)d_out;

    cudaFuncSetAttribute(kA, cudaFuncAttributeMaxDynamicSharedMemorySize, 111616);

    kT<<<512, 256>>>(Wpool);
    kZ<<<128, 256>>>();
    dim3 gA(7, 32);
    kA<<<gA, 256, 111616>>>(x, bpool, Wconv, bconv);
    dim3 gB(4, 32);
    kB<<<gB, 256>>>(centroids);
    dim3 gC(32, 4);
    kC<<<gC, 128>>>(Wproj);
    kD<<<32, 256>>>(bproj, out);
}